// round 5
// baseline (speedup 1.0000x reference)
#include <cuda_runtime.h>
#include <math.h>

#define NB 8
#define NS 512
#define NE 64
#define NH 8
#define NW 8
#define SPLITK 4                    // threads per query row
#define ROWS_PB (256 / SPLITK)      // 64 rows per block
#define KEYS_PT (NS / SPLITK)       // 128 keys per thread

// scratch: attention context in [B, S, E] layout (E = H*8)
__device__ float g_ctx[NB * NS * NE];

typedef unsigned long long u64;

__device__ __forceinline__ u64 pk2(float lo, float hi) {
    u64 r; asm("mov.b64 %0,{%1,%2};" : "=l"(r) : "f"(lo), "f"(hi)); return r;
}
__device__ __forceinline__ void unpk2(u64 v, float& lo, float& hi) {
    asm("mov.b64 {%0,%1},%2;" : "=f"(lo), "=f"(hi) : "l"(v));
}
__device__ __forceinline__ void ffma2(u64& d, u64 a, u64 b) {
    asm("fma.rn.f32x2 %0,%1,%2,%0;" : "+l"(d) : "l"(a), "l"(b));
}
__device__ __forceinline__ void fadd2(u64& d, u64 a) {
    asm("add.rn.f32x2 %0,%0,%1;" : "+l"(d) : "l"(a));
}

// ---------------------------------------------------------------------------
// Kernel 1: analytic quantum heads + self-attention.
//   Block = (b, h, chunk of 64 rows). 4 threads per query row (split-K over
//   keys), combined via shfl. No softmax max pass (|score| <= sqrt(8)).
// ---------------------------------------------------------------------------
__global__ __launch_bounds__(256, 3)
void qattn_kernel(const float* __restrict__ x, const float* __restrict__ theta)
{
    __shared__ __align__(16) float q[NS][NW];   // 16 KB

    const int blk   = blockIdx.x;
    const int chunk = blk & 7;
    const int h     = (blk >> 3) & (NH - 1);
    const int b     = blk >> 6;
    const int tid   = threadIdx.x;

    float th[NW];
#pragma unroll
    for (int k = 0; k < NW; k++) th[k] = __ldg(&theta[k]);

    // ---- build q for ALL 512 tokens of this head (2 per thread) ----
    // e[j>=1] = prod_{k<=j} cos(x_k+th_k);  e[0] = prod_{k=1..7} cos(x_k+th_k)
    for (int s = tid; s < NS; s += 256) {
        const float* xp = x + ((b * NS + s) * NE + h * NW);
        float c[NW];
#pragma unroll
        for (int k = 0; k < NW; k++) c[k] = cosf(xp[k] + th[k]);
        float e[NW];
        float run = c[0];
#pragma unroll
        for (int j = 1; j < NW; j++) { run *= c[j]; e[j] = run; }
        float r = c[NW - 1];
#pragma unroll
        for (int j = NW - 2; j >= 1; j--) r *= c[j];
        e[0] = r;
        *(float4*)&q[s][0] = make_float4(e[0], e[1], e[2], e[3]);
        *(float4*)&q[s][4] = make_float4(e[4], e[5], e[6], e[7]);
    }
    __syncthreads();

    const int sub = tid & (SPLITK - 1);          // key-split lane within row
    const int s   = chunk * ROWS_PB + (tid >> 2);// this thread's query row
    const float scale = 0.35355339059327373f;    // 1/sqrt(8)

    // thread-local scaled query, packed as 4 x f32x2 (broadcast within quad)
    u64 qp[4];
    {
        float4 lo4 = *(const float4*)&q[s][0];
        float4 hi4 = *(const float4*)&q[s][4];
        qp[0] = pk2(lo4.x * scale, lo4.y * scale);
        qp[1] = pk2(lo4.z * scale, lo4.w * scale);
        qp[2] = pk2(hi4.x * scale, hi4.y * scale);
        qp[3] = pk2(hi4.z * scale, hi4.w * scale);
    }

    u64 a2[4] = {0ull, 0ull, 0ull, 0ull};
    float l = 0.f;

    const int t0 = sub * KEYS_PT;
#pragma unroll 4
    for (int ti = 0; ti < KEYS_PT; ti++) {
        const int t = t0 + ti;
        ulonglong2 kA = *(const ulonglong2*)&q[t][0];
        ulonglong2 kB = *(const ulonglong2*)&q[t][4];

        u64 d2 = 0ull, d2b = 0ull;
        ffma2(d2,  qp[0], kA.x);
        ffma2(d2b, qp[1], kA.y);
        ffma2(d2,  qp[2], kB.x);
        ffma2(d2b, qp[3], kB.y);
        fadd2(d2, d2b);
        float dl, dh; unpk2(d2, dl, dh);

        const float e = __expf(dl + dh);   // safe: |score| <= 2.83
        l += e;
        const u64 ep = pk2(e, e);
        ffma2(a2[0], ep, kA.x);
        ffma2(a2[1], ep, kA.y);
        ffma2(a2[2], ep, kB.x);
        ffma2(a2[3], ep, kB.y);
    }

    // combine the 4 split-K partials (lanes sub=0..3 are adjacent)
#pragma unroll
    for (int o = 1; o <= 2; o <<= 1) {
        l += __shfl_xor_sync(0xffffffffu, l, o);
#pragma unroll
        for (int i = 0; i < 4; i++) {
            u64 other = __shfl_xor_sync(0xffffffffu, a2[i], o);
            fadd2(a2[i], other);
        }
    }

    if (sub == 0) {
        const float inv = 1.f / l;
        float o[NW];
#pragma unroll
        for (int i = 0; i < 4; i++) {
            float lo, hi; unpk2(a2[i], lo, hi);
            o[2 * i] = lo * inv; o[2 * i + 1] = hi * inv;
        }
        float* op = g_ctx + ((b * NS + s) * NE + h * NW);
        *(float4*)&op[0] = make_float4(o[0], o[1], o[2], o[3]);
        *(float4*)&op[4] = make_float4(o[4], o[5], o[6], o[7]);
    }
}

// ---------------------------------------------------------------------------
// Kernel 2: out[r][o] = sum_e ctx[r][e] * Wo[o][e] + bo[o]   (4096 x 64 x 64)
// Thread = one output element. Wo row read contiguously (LDG.128, L1-hot).
// grid = 1024 blocks x 4 rows.
// ---------------------------------------------------------------------------
__global__ __launch_bounds__(256, 8)
void proj_kernel(const float* __restrict__ Wo, const float* __restrict__ bo,
                 float* __restrict__ out)
{
    __shared__ __align__(16) float R[4][NE];

    const int tid = threadIdx.x;
    const int rowbase = blockIdx.x * 4;

    // load 4 ctx rows (256 floats), coalesced
    R[tid >> 6][tid & 63] = g_ctx[rowbase * NE + tid];
    __syncthreads();

    const int r = tid >> 6, o = tid & 63;
    const float4* __restrict__ wrow = (const float4*)(Wo + o * NE);

    float acc = __ldg(&bo[o]);
    float acc2 = 0.f;
#pragma unroll
    for (int e4 = 0; e4 < 16; e4 += 2) {
        const float4 w0 = __ldg(&wrow[e4]);
        const float4 c0 = *(const float4*)&R[r][e4 * 4];
        const float4 w1 = __ldg(&wrow[e4 + 1]);
        const float4 c1 = *(const float4*)&R[r][e4 * 4 + 4];
        acc  = fmaf(w0.x, c0.x, acc);
        acc2 = fmaf(w0.y, c0.y, acc2);
        acc  = fmaf(w0.z, c0.z, acc);
        acc2 = fmaf(w0.w, c0.w, acc2);
        acc  = fmaf(w1.x, c1.x, acc);
        acc2 = fmaf(w1.y, c1.y, acc2);
        acc  = fmaf(w1.z, c1.z, acc);
        acc2 = fmaf(w1.w, c1.w, acc2);
    }
    out[(rowbase + r) * NE + o] = acc + acc2;
}

extern "C" void kernel_launch(void* const* d_in, const int* in_sizes, int n_in,
                              void* d_out, int out_size)
{
    const float* x     = (const float*)d_in[0];
    const float* theta = (const float*)d_in[1];
    const float* Wo    = (const float*)d_in[2];
    const float* bo    = (const float*)d_in[3];
    float* out = (float*)d_out;

    qattn_kernel<<<NB * NH * (NS / ROWS_PB), 256>>>(x, theta);
    proj_kernel<<<NB * NS / 4, 256>>>(Wo, bo, out);
}

// round 6
// speedup vs baseline: 2.6884x; 2.6884x over previous
#include <cuda_runtime.h>
#include <math.h>

#define NB 8
#define NS 512
#define NE 64
#define NH 8
#define NW 8

// scratch: attention context in [B, S, E] layout (E = H*8)
__device__ float g_ctx[NB * NS * NE];

typedef unsigned long long u64;

__device__ __forceinline__ u64 pk2(float lo, float hi) {
    u64 r; asm("mov.b64 %0,{%1,%2};" : "=l"(r) : "f"(lo), "f"(hi)); return r;
}
__device__ __forceinline__ void unpk2(u64 v, float& lo, float& hi) {
    asm("mov.b64 {%0,%1},%2;" : "=f"(lo), "=f"(hi) : "l"(v));
}
__device__ __forceinline__ void ffma2(u64& d, u64 a, u64 b) {
    asm("fma.rn.f32x2 %0,%1,%2,%0;" : "+l"(d) : "l"(a), "l"(b));
}
__device__ __forceinline__ void fadd2(u64& d, u64 a) {
    asm("add.rn.f32x2 %0,%0,%1;" : "+l"(d) : "l"(a));
}

// ---------------------------------------------------------------------------
// Kernel 1: analytic quantum heads + self-attention.
//   Block = (b, h, half). Thread = one query row. Single key sweep,
//   no max subtraction (|score| <= sqrt(8)), packed f32x2 FMA, fast __cosf.
// ---------------------------------------------------------------------------
__global__ __launch_bounds__(256, 1)
void qattn_kernel(const float* __restrict__ x, const float* __restrict__ theta)
{
    __shared__ __align__(16) float q[NS][NW];   // 16 KB

    const int blk  = blockIdx.x;
    const int half = blk & 1;
    const int h    = (blk >> 1) & (NH - 1);
    const int b    = blk >> 4;
    const int tid  = threadIdx.x;

    float th[NW];
#pragma unroll
    for (int k = 0; k < NW; k++) th[k] = __ldg(&theta[k]);

    // ---- build q for ALL 512 tokens of this head (2 per thread) ----
    // e[j>=1] = prod_{k<=j} cos(x_k+th_k);  e[0] = prod_{k=1..7} cos(x_k+th_k)
    for (int s = tid; s < NS; s += 256) {
        const float* xp = x + ((b * NS + s) * NE + h * NW);
        float c[NW];
#pragma unroll
        for (int k = 0; k < NW; k++) c[k] = __cosf(xp[k] + th[k]);
        float e[NW];
        float run = c[0];
#pragma unroll
        for (int j = 1; j < NW; j++) { run *= c[j]; e[j] = run; }
        float r = c[NW - 1];
#pragma unroll
        for (int j = NW - 2; j >= 1; j--) r *= c[j];
        e[0] = r;
        *(float4*)&q[s][0] = make_float4(e[0], e[1], e[2], e[3]);
        *(float4*)&q[s][4] = make_float4(e[4], e[5], e[6], e[7]);
    }
    __syncthreads();

    const int s = half * 256 + tid;               // this thread's query row
    const float scale = 0.35355339059327373f;     // 1/sqrt(8)

    // thread-local scaled query, packed as 4 x f32x2
    u64 qp[4];
    {
        float4 lo4 = *(const float4*)&q[s][0];
        float4 hi4 = *(const float4*)&q[s][4];
        qp[0] = pk2(lo4.x * scale, lo4.y * scale);
        qp[1] = pk2(lo4.z * scale, lo4.w * scale);
        qp[2] = pk2(hi4.x * scale, hi4.y * scale);
        qp[3] = pk2(hi4.z * scale, hi4.w * scale);
    }

    u64 a2[4] = {0ull, 0ull, 0ull, 0ull};   // packed output accumulators
    float l = 0.f;

#pragma unroll 4
    for (int t = 0; t < NS; t++) {
        // key/value row as 4 packed f32x2 (two LDS.128, warp-broadcast)
        ulonglong2 kA = *(const ulonglong2*)&q[t][0];
        ulonglong2 kB = *(const ulonglong2*)&q[t][4];

        u64 d2 = 0ull, d2b = 0ull;
        ffma2(d2,  qp[0], kA.x);
        ffma2(d2b, qp[1], kA.y);
        ffma2(d2,  qp[2], kB.x);
        ffma2(d2b, qp[3], kB.y);
        fadd2(d2, d2b);
        float dl, dh; unpk2(d2, dl, dh);

        const float e = __expf(dl + dh);   // safe: |score| <= 2.83
        l += e;
        const u64 ep = pk2(e, e);
        ffma2(a2[0], ep, kA.x);
        ffma2(a2[1], ep, kA.y);
        ffma2(a2[2], ep, kB.x);
        ffma2(a2[3], ep, kB.y);
    }

    const float inv = 1.f / l;
    float o[NW];
#pragma unroll
    for (int i = 0; i < 4; i++) {
        float lo, hi; unpk2(a2[i], lo, hi);
        o[2 * i] = lo * inv; o[2 * i + 1] = hi * inv;
    }
    float* op = g_ctx + ((b * NS + s) * NE + h * NW);
    *(float4*)&op[0] = make_float4(o[0], o[1], o[2], o[3]);
    *(float4*)&op[4] = make_float4(o[4], o[5], o[6], o[7]);
}

// ---------------------------------------------------------------------------
// Kernel 2: out[r][o] = sum_e ctx[r][e] * Wo[o][e] + bo[o]   (4096 x 64 x 64)
// All-smem: WT[e][o] transposed with stride-68 padding (16B-aligned, low
// conflict). 128 blocks x 32 rows; thread = (row, 8 output cols).
// ---------------------------------------------------------------------------
#define WSTR 68
__global__ __launch_bounds__(256, 2)
void proj_kernel(const float* __restrict__ Wo, const float* __restrict__ bo,
                 float* __restrict__ out)
{
    __shared__ __align__(16) float WT[NE * WSTR];   // WT[e*68 + o]
    __shared__ __align__(16) float R[32 * WSTR];    // R[r*68 + e]

    const int tid = threadIdx.x;
    const int rowbase = blockIdx.x * 32;

    // Wo[o*64+e] -> WT[e*68+o]; consecutive tid vary e (stride 68 in smem)
    for (int i = tid; i < NE * NE; i += 256) {
        const int o = i >> 6, e = i & 63;
        WT[e * WSTR + o] = Wo[i];
    }
    // 32 ctx rows, coalesced; store stride-68 rows (consecutive e -> no conflict)
    for (int i = tid; i < 32 * NE; i += 256)
        R[(i >> 6) * WSTR + (i & 63)] = g_ctx[rowbase * NE + i];
    __syncthreads();

    const int r  = tid >> 3;          // 32 rows
    const int o0 = (tid & 7) * 8;     // 8 outputs per thread

    float acc[8];
    {
        const float4 b0 = *(const float4*)&bo[o0];
        const float4 b1 = *(const float4*)&bo[o0 + 4];
        acc[0] = b0.x; acc[1] = b0.y; acc[2] = b0.z; acc[3] = b0.w;
        acc[4] = b1.x; acc[5] = b1.y; acc[6] = b1.z; acc[7] = b1.w;
    }

#pragma unroll 4
    for (int e4 = 0; e4 < NE; e4 += 4) {
        const float4 c4 = *(const float4*)&R[r * WSTR + e4];
        const float cv[4] = {c4.x, c4.y, c4.z, c4.w};
#pragma unroll
        for (int j = 0; j < 4; j++) {
            const int e = e4 + j;
            const float4 w0 = *(const float4*)&WT[e * WSTR + o0];
            const float4 w1 = *(const float4*)&WT[e * WSTR + o0 + 4];
            const float rv = cv[j];
            acc[0] = fmaf(rv, w0.x, acc[0]);
            acc[1] = fmaf(rv, w0.y, acc[1]);
            acc[2] = fmaf(rv, w0.z, acc[2]);
            acc[3] = fmaf(rv, w0.w, acc[3]);
            acc[4] = fmaf(rv, w1.x, acc[4]);
            acc[5] = fmaf(rv, w1.y, acc[5]);
            acc[6] = fmaf(rv, w1.z, acc[6]);
            acc[7] = fmaf(rv, w1.w, acc[7]);
        }
    }

    float* op = out + (rowbase + r) * NE + o0;
    *(float4*)&op[0] = make_float4(acc[0], acc[1], acc[2], acc[3]);
    *(float4*)&op[4] = make_float4(acc[4], acc[5], acc[6], acc[7]);
}

extern "C" void kernel_launch(void* const* d_in, const int* in_sizes, int n_in,
                              void* d_out, int out_size)
{
    const float* x     = (const float*)d_in[0];
    const float* theta = (const float*)d_in[1];
    const float* Wo    = (const float*)d_in[2];
    const float* bo    = (const float*)d_in[3];
    float* out = (float*)d_out;

    qattn_kernel<<<NB * NH * 2, 256>>>(x, theta);
    proj_kernel<<<NB * NS / 32, 256>>>(Wo, bo, out);
}